// round 12
// baseline (speedup 1.0000x reference)
#include <cuda_runtime.h>
#include <cuda_fp16.h>
#include <math.h>
#include <stdint.h>

#define NN    20000
#define NPAD  20096            // 157*128
#define EE    320000
#define FIN   518
#define KP1   544
#define DD    128
#define EDIM  32
#define HH    4
#define RR    26
#define HID   256
#define SCANB ((NN + 127) / 128)
#define PADB  ((int)(((size_t)NPAD * KP1) / 256))
#define ZERB  ((NN + 256) / 256)
#define C1B   ((KP1 * HID) / 256)
#define C2B   ((HID * DD) / 256)
#define C3B   ((2 * DD * HH * DD) / 256)

// ---------------- scratch ----------------
__device__ __half g_xp[(size_t)NPAD * KP1];
__device__ __half g_h1h[(size_t)NPAD * HID];
__device__ __half g_xh[(size_t)NPAD * DD];
__device__ __half g_hHh[(size_t)NPAD * HH * DD];
__device__ __half g_w1h[(size_t)KP1 * HID];
__device__ __half g_w2h[(size_t)HID * DD];
__device__ __half g_linh[2][(size_t)DD * HH * DD];
__device__ __align__(16) float g_asd[2][NN * 8];
__device__ __align__(16) float g_tab[2][RR][HH];
__device__ float g_ws[2][8][DD];
__device__ int   g_deg[NN + 1];
__device__ int   g_off[NN + 1];
__device__ int   g_cur[NN];
__device__ int   g_esd[EE];          // packed: src | (et << 20)
__device__ unsigned long long g_scanstate[SCANB];

// ---------------- setup ----------------
__global__ void setup(const float* __restrict__ x, const float* __restrict__ rel,
                      const float* __restrict__ line0, const float* __restrict__ atte0,
                      const float* __restrict__ line1, const float* __restrict__ atte1,
                      const float* __restrict__ lin0, const float* __restrict__ atts0,
                      const float* __restrict__ attd0,
                      const float* __restrict__ lin1, const float* __restrict__ atts1,
                      const float* __restrict__ attd1,
                      const float* __restrict__ w1, const float* __restrict__ w2) {
    int b = blockIdx.x, tid = threadIdx.x;
    if (b < PADB) {
        size_t i = (size_t)b * 256 + tid;
        int n = (int)(i / KP1), c = (int)(i % KP1);
        float v = (n < NN && c < FIN) ? x[(size_t)n * FIN + c] : 0.0f;
        g_xp[i] = __float2half(v);
        return;
    }
    b -= PADB;
    if (b < ZERB) {
        int i = b * 256 + tid;
        if (i <= NN) g_deg[i] = 0;
        return;
    }
    b -= ZERB;
    if (b == 0) {
        __shared__ float we[2][HH][EDIM];
        if (tid < 2 * HH * EDIM) {
            int L = tid >> 7, rem = tid & 127;
            int h = rem / EDIM, c = rem % EDIM;
            const float* line = L ? line1 : line0;
            const float* atte = L ? atte1 : atte0;
            float s = 0.0f;
            for (int d = 0; d < DD; d++)
                s += line[(size_t)c * (HH * DD) + h * DD + d] * atte[h * DD + d];
            we[L][h][c] = s;
        }
        __syncthreads();
        if (tid < 2 * RR * HH) {
            int L = tid / (RR * HH), rem = tid % (RR * HH);
            int r = rem / HH, h = rem % HH;
            float s = 0.0f;
            for (int c = 0; c < EDIM; c++)
                s += rel[r * EDIM + c] * we[L][h][c];
            g_tab[L][r][h] = s;
        }
        if (tid < SCANB) g_scanstate[tid] = 0ULL;
        return;
    }
    b -= 1;
    if (b < 8) {
        int idx = b * 256 + tid;
        if (idx < 2 * 8 * DD) {
            int L = idx / (8 * DD), rem = idx % (8 * DD);
            int h8 = rem / DD, k = rem % DD;
            const float* lin = L ? lin1 : lin0;
            const float* att;
            int h = h8 & 3;
            if (h8 < 4) att = L ? atts1 : atts0;
            else        att = L ? attd1 : attd0;
            float s = 0.0f;
            for (int d = 0; d < DD; d++)
                s += lin[(size_t)k * (HH * DD) + h * DD + d] * att[h * DD + d];
            g_ws[L][h8][k] = s;
        }
        return;
    }
    b -= 8;
    if (b < C1B) {
        int i = b * 256 + tid;
        int k = i / HID, n = i % HID;
        g_w1h[i] = __float2half(k < FIN ? w1[(size_t)k * HID + n] : 0.0f);
        return;
    }
    b -= C1B;
    if (b < C2B) {
        int i = b * 256 + tid;
        g_w2h[i] = __float2half(w2[i]);
        return;
    }
    b -= C2B;
    {
        int i = b * 256 + tid;
        int L = i / (DD * HH * DD), r = i % (DD * HH * DD);
        const float* lin = L ? lin1 : lin0;
        g_linh[L][r] = __float2half(lin[r]);
    }
}

__global__ void count_deg(const int* __restrict__ dst) {
    int e = blockIdx.x * blockDim.x + threadIdx.x;
    if (e < EE) atomicAdd(&g_deg[dst[e]], 1);
}

__global__ void scan_lookback() {
    int b = blockIdx.x, tid = threadIdx.x;
    int lane = tid & 31, warp = tid >> 5;
    int i = b * 128 + tid;
    int v = (i < NN) ? g_deg[i] : 0;
    int incl = v;
#pragma unroll
    for (int o = 1; o < 32; o <<= 1) {
        int t = __shfl_up_sync(0xffffffffu, incl, o);
        if (lane >= o) incl += t;
    }
    __shared__ int wsum[4];
    __shared__ int s_prev;
    if (lane == 31) wsum[warp] = incl;
    __syncthreads();
    int wbase = 0;
    for (int w = 0; w < warp; w++) wbase += wsum[w];
    int incl_b = wbase + incl;
    int total = wsum[0] + wsum[1] + wsum[2] + wsum[3];

    if (tid == 0) {
        if (b == 0) {
            atomicExch(&g_scanstate[0], (2ULL << 32) | (unsigned)total);
            s_prev = 0;
        } else {
            atomicExch(&g_scanstate[b], (1ULL << 32) | (unsigned)total);
            long long run = 0;
            int j = b - 1;
            while (1) {
                unsigned long long st;
                do { st = atomicOr(&g_scanstate[j], 0ULL); } while ((st >> 32) == 0ULL);
                run += (long long)(st & 0xffffffffULL);
                if ((st >> 32) == 2ULL) break;
                j--;
            }
            s_prev = (int)run;
            atomicExch(&g_scanstate[b], (2ULL << 32) | (unsigned)(run + total));
        }
    }
    __syncthreads();
    int excl = s_prev + incl_b - v;
    if (i < NN) {
        g_off[i] = excl;
        g_cur[i] = excl;
        if (i == NN - 1) g_off[NN] = excl + v;
    }
}

__global__ void scatter_csr(const int* __restrict__ src, const int* __restrict__ dst,
                            const int* __restrict__ et) {
    int e = blockIdx.x * blockDim.x + threadIdx.x;
    if (e >= EE) return;
    int pos = atomicAdd(&g_cur[dst[e]], 1);
    g_esd[pos] = src[e] | (et[e] << 20);
}

// ---------------- shared GEMM helpers ----------------
__device__ __forceinline__ uint32_t h2u(__half2 h) {
    return *reinterpret_cast<uint32_t*>(&h);
}
__device__ __forceinline__ void ldsm_x4(uint32_t* r, uint32_t addr) {
    asm volatile("ldmatrix.sync.aligned.m8n8.x4.shared.b16 {%0,%1,%2,%3}, [%4];"
                 : "=r"(r[0]), "=r"(r[1]), "=r"(r[2]), "=r"(r[3]) : "r"(addr));
}
__device__ __forceinline__ void ldsm_x4_t(uint32_t* r, uint32_t addr) {
    asm volatile("ldmatrix.sync.aligned.m8n8.x4.trans.shared.b16 {%0,%1,%2,%3}, [%4];"
                 : "=r"(r[0]), "=r"(r[1]), "=r"(r[2]), "=r"(r[3]) : "r"(addr));
}
__device__ __forceinline__ void hmma(float* c, const uint32_t* a, uint32_t b0, uint32_t b1) {
    asm volatile(
        "mma.sync.aligned.m16n8k16.row.col.f32.f16.f16.f32 "
        "{%0,%1,%2,%3}, {%4,%5,%6,%7}, {%8,%9}, {%0,%1,%2,%3};\n"
        : "+f"(c[0]), "+f"(c[1]), "+f"(c[2]), "+f"(c[3])
        : "r"(a[0]), "r"(a[1]), "r"(a[2]), "r"(a[3]), "r"(b0), "r"(b1));
}
__device__ __forceinline__ void cp16(uint32_t dst, const void* src) {
    asm volatile("cp.async.cg.shared.global [%0], [%1], 16;" :: "r"(dst), "l"(src));
}
__device__ __forceinline__ void cp_commit() {
    asm volatile("cp.async.commit_group;" ::: "memory");
}
__device__ __forceinline__ void cp_wait2() {
    asm volatile("cp.async.wait_group 2;" ::: "memory");
}
__device__ __forceinline__ void cp_wait1() {
    asm volatile("cp.async.wait_group 1;" ::: "memory");
}

// ---------------- narrow GEMM (BN=128, 4-stage) — used for GEMM2 ----------------
#define STAGES   4
#define A_STAGE  10240       // 128 rows * 80 B
#define B_STAGE  8704        // 32 rows * 272 B
#define SMEM_SZ  (STAGES * (A_STAGE + B_STAGE))   // 75776

__global__ __launch_bounds__(256)
void mma_gemm(const __half* __restrict__ A, const __half* __restrict__ B,
              const float* __restrict__ bias, __half* __restrict__ C,
              int K, int Nn, int doRelu) {
    extern __shared__ char smem[];
    const uint32_t smem_u = (uint32_t)__cvta_generic_to_shared(smem);
    const uint32_t as_u = smem_u;
    const uint32_t bs_u = smem_u + STAGES * A_STAGE;

    const int tid = threadIdx.x;
    const int warp = tid >> 5, lane = tid & 31;
    const int g = lane >> 2, tg = lane & 3;
    const int warpM = warp >> 1, warpN = warp & 1;
    const int rowBase = blockIdx.y * 128, colBase = blockIdx.x * 128;

    const int a_row = tid >> 1, a_ch = (tid & 1) * 2;
    const uint32_t a_dst = as_u + a_row * 80 + a_ch * 16;
    const __half* a_src = A + (size_t)(rowBase + a_row) * K + a_ch * 8;
    const int b_row = tid >> 3, b_ch = (tid & 7) * 2;
    const uint32_t b_dst = bs_u + b_row * 272 + b_ch * 16;
    const __half* b_src = B + (size_t)b_row * Nn + colBase + b_ch * 8;

    const int lm_row = ((lane >> 3) & 1) * 8 + (lane & 7);
    const int lm_hi  = (lane >= 16) ? 8 : 0;

    float acc[2][8][4];
#pragma unroll
    for (int mi = 0; mi < 2; mi++)
#pragma unroll
        for (int ni = 0; ni < 8; ni++)
#pragma unroll
            for (int r = 0; r < 4; r++) acc[mi][ni][r] = 0.0f;

    const int nk = K / 32;

#define ISSUE(S, T)                                                        \
    {                                                                      \
        int k0 = (T) * 32;                                                 \
        cp16(a_dst + (S) * A_STAGE, a_src + k0);                           \
        cp16(a_dst + (S) * A_STAGE + 16, a_src + k0 + 8);                  \
        cp16(b_dst + (S) * B_STAGE, b_src + (size_t)k0 * Nn);              \
        cp16(b_dst + (S) * B_STAGE + 16, b_src + (size_t)k0 * Nn + 8);     \
    }

#pragma unroll
    for (int s = 0; s < STAGES - 1; s++) {
        if (s < nk) ISSUE(s, s)
        cp_commit();
    }

    for (int t = 0; t < nk; t++) {
        cp_wait2();
        __syncthreads();
        if (t + STAGES - 1 < nk) ISSUE((t + STAGES - 1) & 3, t + STAGES - 1)
        cp_commit();

        const uint32_t as_s = as_u + (t & 3) * A_STAGE;
        const uint32_t bs_s = bs_u + (t & 3) * B_STAGE;
#pragma unroll
        for (int ks = 0; ks < 2; ks++) {
            uint32_t a[2][4];
#pragma unroll
            for (int mi = 0; mi < 2; mi++) {
                int row = warpM * 32 + mi * 16 + lm_row;
                ldsm_x4(a[mi], as_s + row * 80 + (ks * 16 + lm_hi) * 2);
            }
            uint32_t bf[4][4];
#pragma unroll
            for (int nj = 0; nj < 4; nj++) {
                int col = warpN * 64 + nj * 16 + lm_hi;
                ldsm_x4_t(bf[nj], bs_s + (ks * 16 + lm_row) * 272 + col * 2);
            }
#pragma unroll
            for (int ni = 0; ni < 8; ni++) {
                uint32_t b0 = bf[ni >> 1][(ni & 1) * 2];
                uint32_t b1 = bf[ni >> 1][(ni & 1) * 2 + 1];
#pragma unroll
                for (int mi = 0; mi < 2; mi++)
                    hmma(acc[mi][ni], a[mi], b0, b1);
            }
        }
    }
#undef ISSUE

#pragma unroll
    for (int mi = 0; mi < 2; mi++) {
        int r0 = rowBase + warpM * 32 + mi * 16 + g;
#pragma unroll
        for (int ni = 0; ni < 8; ni++) {
            int c0 = colBase + warpN * 64 + ni * 8 + tg * 2;
            float bb0 = bias ? bias[c0] : 0.0f;
            float bb1 = bias ? bias[c0 + 1] : 0.0f;
            float v0 = acc[mi][ni][0] + bb0;
            float v1 = acc[mi][ni][1] + bb1;
            float v2 = acc[mi][ni][2] + bb0;
            float v3 = acc[mi][ni][3] + bb1;
            if (doRelu) {
                v0 = fmaxf(v0, 0.f); v1 = fmaxf(v1, 0.f);
                v2 = fmaxf(v2, 0.f); v3 = fmaxf(v3, 0.f);
            }
            __half2 p0 = __floats2half2_rn(v0, v1);
            __half2 p1 = __floats2half2_rn(v2, v3);
            *(uint32_t*)(C + (size_t)r0 * Nn + c0) = h2u(p0);
            *(uint32_t*)(C + (size_t)(r0 + 8) * Nn + c0) = h2u(p1);
        }
    }
}

// ---------------- wide GEMM (BM=128, BN=256, 3-stage) — GEMM1 & GEMM3 ----------------
#define WSTAGES   3
#define WA_STAGE  10240       // 128 rows * 80 B
#define WB_STAGE  16896      // 32 rows * 528 B
#define WSMEM_SZ  (WSTAGES * (WA_STAGE + WB_STAGE))   // 81408

__global__ __launch_bounds__(256)
void mma_gemm_wide(const __half* __restrict__ A, const __half* __restrict__ B,
                   const float* __restrict__ bias, __half* __restrict__ C,
                   int K, int Nn, int doRelu) {
    extern __shared__ char smem[];
    const uint32_t smem_u = (uint32_t)__cvta_generic_to_shared(smem);
    const uint32_t as_u = smem_u;
    const uint32_t bs_u = smem_u + WSTAGES * WA_STAGE;

    const int tid = threadIdx.x;
    const int warp = tid >> 5, lane = tid & 31;
    const int g = lane >> 2, tg = lane & 3;
    const int warpM = warp >> 2, warpN = warp & 3;        // 2x4 warps, warp tile 64x64
    const int rowBase = blockIdx.y * 128, colBase = blockIdx.x * 256;

    const int a_row = tid >> 1, a_ch = (tid & 1) * 2;
    const uint32_t a_dst = as_u + a_row * 80 + a_ch * 16;
    const __half* a_src = A + (size_t)(rowBase + a_row) * K + a_ch * 8;
    const int b_row = tid >> 3;                            // 32 rows
    const int b_c0 = (tid & 7) * 4;                        // 4 chunks of 16B
    const uint32_t b_dst = bs_u + b_row * 528 + b_c0 * 16;
    const __half* b_src = B + (size_t)b_row * Nn + colBase + b_c0 * 8;

    const int lm_row = ((lane >> 3) & 1) * 8 + (lane & 7);
    const int lm_hi  = (lane >= 16) ? 8 : 0;

    float acc[4][8][4];
#pragma unroll
    for (int mi = 0; mi < 4; mi++)
#pragma unroll
        for (int ni = 0; ni < 8; ni++)
#pragma unroll
            for (int r = 0; r < 4; r++) acc[mi][ni][r] = 0.0f;

    const int nk = K / 32;

#define WISSUE(S, T)                                                          \
    {                                                                         \
        int k0 = (T) * 32;                                                    \
        cp16(a_dst + (S) * WA_STAGE, a_src + k0);                             \
        cp16(a_dst + (S) * WA_STAGE + 16, a_src + k0 + 8);                    \
        const __half* bp = b_src + (size_t)k0 * Nn;                           \
        uint32_t bd = b_dst + (S) * WB_STAGE;                                 \
        cp16(bd, bp); cp16(bd + 16, bp + 8);                                  \
        cp16(bd + 32, bp + 16); cp16(bd + 48, bp + 24);                       \
    }

    // prologue: stages 0,1
    WISSUE(0, 0) cp_commit();
    if (nk > 1) { WISSUE(1, 1) } cp_commit();

    int st = 0, st2 = 2;                     // compute stage, issue stage
    for (int t = 0; t < nk; t++) {
        cp_wait1();
        __syncthreads();
        if (t + 2 < nk) WISSUE(st2, t + 2)
        cp_commit();

        const uint32_t as_s = as_u + st * WA_STAGE;
        const uint32_t bs_s = bs_u + st * WB_STAGE;
#pragma unroll
        for (int ks = 0; ks < 2; ks++) {
            uint32_t a[4][4];
#pragma unroll
            for (int mi = 0; mi < 4; mi++) {
                int row = warpM * 64 + mi * 16 + lm_row;
                ldsm_x4(a[mi], as_s + row * 80 + (ks * 16 + lm_hi) * 2);
            }
            uint32_t bf[4][4];
#pragma unroll
            for (int nj = 0; nj < 4; nj++) {
                int col = warpN * 64 + nj * 16 + lm_hi;
                ldsm_x4_t(bf[nj], bs_s + (ks * 16 + lm_row) * 528 + col * 2);
            }
#pragma unroll
            for (int ni = 0; ni < 8; ni++) {
                uint32_t b0 = bf[ni >> 1][(ni & 1) * 2];
                uint32_t b1 = bf[ni >> 1][(ni & 1) * 2 + 1];
#pragma unroll
                for (int mi = 0; mi < 4; mi++)
                    hmma(acc[mi][ni], a[mi], b0, b1);
            }
        }
        st = (st == 2) ? 0 : st + 1;
        st2 = (st2 == 2) ? 0 : st2 + 1;
    }
#undef WISSUE

#pragma unroll
    for (int mi = 0; mi < 4; mi++) {
        int r0 = rowBase + warpM * 64 + mi * 16 + g;
#pragma unroll
        for (int ni = 0; ni < 8; ni++) {
            int c0 = colBase + warpN * 64 + ni * 8 + tg * 2;
            float bb0 = bias ? bias[c0] : 0.0f;
            float bb1 = bias ? bias[c0 + 1] : 0.0f;
            float v0 = acc[mi][ni][0] + bb0;
            float v1 = acc[mi][ni][1] + bb1;
            float v2 = acc[mi][ni][2] + bb0;
            float v3 = acc[mi][ni][3] + bb1;
            if (doRelu) {
                v0 = fmaxf(v0, 0.f); v1 = fmaxf(v1, 0.f);
                v2 = fmaxf(v2, 0.f); v3 = fmaxf(v3, 0.f);
            }
            __half2 p0 = __floats2half2_rn(v0, v1);
            __half2 p1 = __floats2half2_rn(v2, v3);
            *(uint32_t*)(C + (size_t)r0 * Nn + c0) = h2u(p0);
            *(uint32_t*)(C + (size_t)(r0 + 8) * Nn + c0) = h2u(p1);
        }
    }
}

// ---------------- a_s/a_d for layer 0 from g_xh (warp per node) ----------------
__global__ void asd0() {
    int n = blockIdx.x * 8 + (threadIdx.x >> 5);
    int lane = threadIdx.x & 31;
    if (n >= NN) return;
    uint2 u = *(const uint2*)(g_xh + (size_t)n * DD + lane * 4);
    float2 xa = __half22float2(*(__half2*)&u.x);
    float2 xb = __half22float2(*(__half2*)&u.y);
    float r[8];
#pragma unroll
    for (int h = 0; h < 8; h++) {
        const float* w = &g_ws[0][h][lane * 4];
        float p = xa.x * w[0] + xa.y * w[1] + xb.x * w[2] + xb.y * w[3];
#pragma unroll
        for (int o = 16; o; o >>= 1) p += __shfl_xor_sync(0xffffffffu, p, o);
        r[h] = p;
    }
    if (lane < 8) g_asd[0][n * 8 + lane] = r[lane];
}

// fused GAT: staged edge metadata + cooperative weights + gather + softmax + epilogue
__global__ void gat_node(const float* __restrict__ bias, float* __restrict__ outF, int L) {
    int n = blockIdx.x;
    int tid = threadIdx.x;      // 128
    int head = tid >> 5;
    __shared__ float tab_sm[RR * HH];
    __shared__ float s_adn[4];
    __shared__ int   sval[128];
    __shared__ float wbuf[512];
    __shared__ float sbuf[512];
    const float* asd = g_asd[L];
    if (tid < RR * HH) tab_sm[tid] = ((const float*)g_tab)[L * RR * HH + tid];
    if (tid < 4) s_adn[tid] = asd[n * 8 + 4 + tid];
    __syncthreads();

    int p0 = g_off[n], p1 = g_off[n + 1];
    int deg = p1 - p0;
    const uint2* hrow = (const uint2*)g_hHh;
    float4 acc = make_float4(0.f, 0.f, 0.f, 0.f);
    float wsum = 0.0f, tsum = 0.0f;

    for (int base = p0; base < p1; base += 128) {
        int m = min(128, p1 - base);
        if (tid < m) {
            int v = g_esd[base + tid];
            sval[tid] = v;
            int s = v & 0xFFFFF, t = v >> 20;
            float4 as4 = *(const float4*)(asd + s * 8);
            const float* tb = &tab_sm[t * HH];
            float r0 = as4.x + s_adn[0] + tb[0]; r0 = r0 > 0.f ? r0 : 0.2f * r0;
            float r1 = as4.y + s_adn[1] + tb[1]; r1 = r1 > 0.f ? r1 : 0.2f * r1;
            float r2 = as4.z + s_adn[2] + tb[2]; r2 = r2 > 0.f ? r2 : 0.2f * r2;
            float r3 = as4.w + s_adn[3] + tb[3]; r3 = r3 > 0.f ? r3 : 0.2f * r3;
            float4 w4 = make_float4(__expf(r0), __expf(r1), __expf(r2), __expf(r3));
            *(float4*)&wbuf[tid * 4] = w4;
        }
        __syncthreads();
        int e = 0;
        for (; e + 4 <= m; e += 4) {
            int v0 = sval[e], v1 = sval[e + 1], v2 = sval[e + 2], v3 = sval[e + 3];
            float w0 = wbuf[e * 4 + head];
            float w1 = wbuf[(e + 1) * 4 + head];
            float w2 = wbuf[(e + 2) * 4 + head];
            float w3 = wbuf[(e + 3) * 4 + head];
            uint2 u0 = hrow[(size_t)(v0 & 0xFFFFF) * 128 + tid];
            uint2 u1 = hrow[(size_t)(v1 & 0xFFFFF) * 128 + tid];
            uint2 u2 = hrow[(size_t)(v2 & 0xFFFFF) * 128 + tid];
            uint2 u3 = hrow[(size_t)(v3 & 0xFFFFF) * 128 + tid];
            wsum += (w0 + w1) + (w2 + w3);
            tsum += tab_sm[(v0 >> 20) * HH + head] + tab_sm[(v1 >> 20) * HH + head]
                  + tab_sm[(v2 >> 20) * HH + head] + tab_sm[(v3 >> 20) * HH + head];
            float2 a0 = __half22float2(*(__half2*)&u0.x), b0 = __half22float2(*(__half2*)&u0.y);
            float2 a1 = __half22float2(*(__half2*)&u1.x), b1 = __half22float2(*(__half2*)&u1.y);
            float2 a2 = __half22float2(*(__half2*)&u2.x), b2 = __half22float2(*(__half2*)&u2.y);
            float2 a3 = __half22float2(*(__half2*)&u3.x), b3 = __half22float2(*(__half2*)&u3.y);
            acc.x += w0 * a0.x + w1 * a1.x + w2 * a2.x + w3 * a3.x;
            acc.y += w0 * a0.y + w1 * a1.y + w2 * a2.y + w3 * a3.y;
            acc.z += w0 * b0.x + w1 * b1.x + w2 * b2.x + w3 * b3.x;
            acc.w += w0 * b0.y + w1 * b1.y + w2 * b2.y + w3 * b3.y;
        }
        for (; e < m; e++) {
            int v = sval[e];
            int s = v & 0xFFFFF;
            float w = wbuf[e * 4 + head];
            uint2 u = hrow[(size_t)s * 128 + tid];
            wsum += w;
            tsum += tab_sm[(v >> 20) * HH + head];
            float2 f0 = __half22float2(*(__half2*)&u.x);
            float2 f1 = __half22float2(*(__half2*)&u.y);
            acc.x += w * f0.x; acc.y += w * f0.y;
            acc.z += w * f1.x; acc.w += w * f1.y;
        }
        __syncthreads();
    }
    // self loop
    {
        float asn = asd[n * 8 + head];
        float adn = s_adn[head];
        float sr = asn + adn + tsum / fmaxf((float)deg, 1.0f);
        sr = sr > 0.f ? sr : 0.2f * sr;
        float wself = __expf(sr);
        uint2 u = hrow[(size_t)n * 128 + tid];
        float2 f0 = __half22float2(*(__half2*)&u.x);
        float2 f1 = __half22float2(*(__half2*)&u.y);
        acc.x += wself * f0.x; acc.y += wself * f0.y;
        acc.z += wself * f1.x; acc.w += wself * f1.y;
        float inv = 1.0f / (wsum + wself + 1e-16f);
        acc.x *= inv; acc.y *= inv; acc.z *= inv; acc.w *= inv;
    }
    *(float4*)&sbuf[tid * 4] = acc;
    __syncthreads();
    if (tid < 32) {
        float ov[4];
#pragma unroll
        for (int j = 0; j < 4; j++) {
            int d = tid * 4 + j;
            float v = 0.25f * (sbuf[d] + sbuf[128 + d] + sbuf[256 + d] + sbuf[384 + d]) + bias[d];
            v = fmaxf(v, 0.0f);
            ov[j] = v;
        }
        if (L == 0) {
            __half2 p0 = __floats2half2_rn(ov[0], ov[1]);
            __half2 p1 = __floats2half2_rn(ov[2], ov[3]);
            uint2 pk = make_uint2(h2u(p0), h2u(p1));
            *(uint2*)(g_xh + (size_t)n * DD + tid * 4) = pk;
            float r[8];
#pragma unroll
            for (int h = 0; h < 8; h++) {
                const float* w = &g_ws[1][h][tid * 4];
                float pp = ov[0] * w[0] + ov[1] * w[1] + ov[2] * w[2] + ov[3] * w[3];
#pragma unroll
                for (int o = 16; o; o >>= 1) pp += __shfl_xor_sync(0xffffffffu, pp, o);
                r[h] = pp;
            }
            if (tid < 8) g_asd[1][n * 8 + tid] = r[tid];
        } else {
#pragma unroll
            for (int j = 0; j < 4; j++)
                outF[(size_t)n * DD + tid * 4 + j] = ov[j];
        }
    }
}

// ---------------- host ----------------
template <typename T>
static T* symaddr(const void* s) {
    void* p = nullptr;
    cudaGetSymbolAddress(&p, s);
    return (T*)p;
}

extern "C" void kernel_launch(void* const* d_in, const int* in_sizes, int n_in,
                              void* d_out, int out_size) {
    const float* x   = (const float*)d_in[0];
    const int*   ei  = (const int*)d_in[1];
    const int*   et  = (const int*)d_in[2];
    const float* w1  = (const float*)d_in[3];
    const float* b1  = (const float*)d_in[4];
    const float* w2  = (const float*)d_in[5];
    const float* b2  = (const float*)d_in[6];
    const float* rel = (const float*)d_in[7];
    const float* lin[2]  = {(const float*)d_in[8],  (const float*)d_in[14]};
    const float* line[2] = {(const float*)d_in[9],  (const float*)d_in[15]};
    const float* atts[2] = {(const float*)d_in[10], (const float*)d_in[16]};
    const float* attd[2] = {(const float*)d_in[11], (const float*)d_in[17]};
    const float* atte[2] = {(const float*)d_in[12], (const float*)d_in[18]};
    const float* bias[2] = {(const float*)d_in[13], (const float*)d_in[19]};
    const int* srcp = ei;
    const int* dstp = ei + EE;

    __half* pxp  = symaddr<__half>(g_xp);
    __half* ph1  = symaddr<__half>(g_h1h);
    __half* pxh  = symaddr<__half>(g_xh);
    __half* phH  = symaddr<__half>(g_hHh);
    __half* pw1  = symaddr<__half>(g_w1h);
    __half* pw2  = symaddr<__half>(g_w2h);
    __half* pl0  = symaddr<__half>(g_linh);
    __half* pl1  = pl0 + (size_t)DD * HH * DD;

    cudaFuncSetAttribute(mma_gemm, cudaFuncAttributeMaxDynamicSharedMemorySize, SMEM_SZ);
    cudaFuncSetAttribute(mma_gemm_wide, cudaFuncAttributeMaxDynamicSharedMemorySize, WSMEM_SZ);

    setup<<<PADB + ZERB + 1 + 8 + C1B + C2B + C3B, 256>>>(
        x, rel, line[0], atte[0], line[1], atte[1],
        lin[0], atts[0], attd[0], lin[1], atts[1], attd[1], w1, w2);
    count_deg<<<(EE + 255) / 256, 256>>>(dstp);
    scan_lookback<<<SCANB, 128>>>();
    mma_gemm_wide<<<dim3(HID / 256, NPAD / 128), 256, WSMEM_SZ>>>(pxp, pw1, b1, ph1, KP1, HID, 1);
    scatter_csr<<<(EE + 255) / 256, 256>>>(srcp, dstp, et);
    mma_gemm<<<dim3(DD / 128, NPAD / 128), 256, SMEM_SZ>>>(ph1, pw2, b2, pxh, HID, DD, 0);
    asd0<<<(NN + 7) / 8, 256>>>();

    for (int L = 0; L < 2; L++) {
        mma_gemm_wide<<<dim3((HH * DD) / 256, NPAD / 128), 256, WSMEM_SZ>>>(
            pxh, L ? pl1 : pl0, nullptr, phH, DD, HH * DD, 0);
        gat_node<<<NN, 128>>>(bias[L], (float*)d_out, L);
    }
}

// round 14
// speedup vs baseline: 1.1372x; 1.1372x over previous
#include <cuda_runtime.h>
#include <cuda_fp16.h>
#include <math.h>
#include <stdint.h>

#define NN    20000
#define NPAD  20096            // 157*128
#define EE    320000
#define FIN   518
#define KP1   544
#define DD    128
#define EDIM  32
#define HH    4
#define RR    26
#define HID   256
#define SCANB ((NN + 127) / 128)
#define PADB  ((int)(((size_t)NPAD * KP1) / 256))
#define C1B   ((KP1 * HID) / 256)
#define C2B   ((HID * DD) / 256)
#define C3B   ((2 * DD * HH * DD) / 256)

// ---------------- scratch ----------------
__device__ __half g_xp[(size_t)NPAD * KP1];
__device__ __half g_h1h[(size_t)NPAD * HID];
__device__ __half g_xh[(size_t)NPAD * DD];
__device__ __half g_hHh[(size_t)NPAD * HH * DD];
__device__ __half g_w1h[(size_t)KP1 * HID];
__device__ __half g_w2h[(size_t)HID * DD];
__device__ __half g_linh[2][(size_t)DD * HH * DD];
__device__ __align__(16) float g_asd[2][NN * 8];
__device__ __align__(16) float g_tab[2][RR][HH];
__device__ float g_ws[2][8][DD];
__device__ int   g_deg[NN + 1];
__device__ int   g_off[NN + 1];
__device__ int   g_cur[NN];
__device__ int   g_esd[EE];          // packed: src | (et << 20)
__device__ unsigned long long g_scanstate[SCANB];

// ---------------- setup (dense-chain only: pads + weight converts + tab + ws) ----------------
__global__ void setup(const float* __restrict__ x, const float* __restrict__ rel,
                      const float* __restrict__ line0, const float* __restrict__ atte0,
                      const float* __restrict__ line1, const float* __restrict__ atte1,
                      const float* __restrict__ lin0, const float* __restrict__ atts0,
                      const float* __restrict__ attd0,
                      const float* __restrict__ lin1, const float* __restrict__ atts1,
                      const float* __restrict__ attd1,
                      const float* __restrict__ w1, const float* __restrict__ w2) {
    int b = blockIdx.x, tid = threadIdx.x;
    if (b < PADB) {
        size_t i = (size_t)b * 256 + tid;
        int n = (int)(i / KP1), c = (int)(i % KP1);
        float v = (n < NN && c < FIN) ? x[(size_t)n * FIN + c] : 0.0f;
        g_xp[i] = __float2half(v);
        return;
    }
    b -= PADB;
    if (b == 0) {
        __shared__ float we[2][HH][EDIM];
        if (tid < 2 * HH * EDIM) {
            int L = tid >> 7, rem = tid & 127;
            int h = rem / EDIM, c = rem % EDIM;
            const float* line = L ? line1 : line0;
            const float* atte = L ? atte1 : atte0;
            float s = 0.0f;
            for (int d = 0; d < DD; d++)
                s += line[(size_t)c * (HH * DD) + h * DD + d] * atte[h * DD + d];
            we[L][h][c] = s;
        }
        __syncthreads();
        if (tid < 2 * RR * HH) {
            int L = tid / (RR * HH), rem = tid % (RR * HH);
            int r = rem / HH, h = rem % HH;
            float s = 0.0f;
            for (int c = 0; c < EDIM; c++)
                s += rel[r * EDIM + c] * we[L][h][c];
            g_tab[L][r][h] = s;
        }
        return;
    }
    b -= 1;
    if (b < 8) {
        int idx = b * 256 + tid;
        if (idx < 2 * 8 * DD) {
            int L = idx / (8 * DD), rem = idx % (8 * DD);
            int h8 = rem / DD, k = rem % DD;
            const float* lin = L ? lin1 : lin0;
            const float* att;
            int h = h8 & 3;
            if (h8 < 4) att = L ? atts1 : atts0;
            else        att = L ? attd1 : attd0;
            float s = 0.0f;
            for (int d = 0; d < DD; d++)
                s += lin[(size_t)k * (HH * DD) + h * DD + d] * att[h * DD + d];
            g_ws[L][h8][k] = s;
        }
        return;
    }
    b -= 8;
    if (b < C1B) {
        int i = b * 256 + tid;
        int k = i / HID, n = i % HID;
        g_w1h[i] = __float2half(k < FIN ? w1[(size_t)k * HID + n] : 0.0f);
        return;
    }
    b -= C1B;
    if (b < C2B) {
        int i = b * 256 + tid;
        g_w2h[i] = __float2half(w2[i]);
        return;
    }
    b -= C2B;
    {
        int i = b * 256 + tid;
        int L = i / (DD * HH * DD), r = i % (DD * HH * DD);
        const float* lin = L ? lin1 : lin0;
        g_linh[L][r] = __float2half(lin[r]);
    }
}

// ---------------- CSR chain (stream 2) ----------------
__global__ void zero_deg() {
    int i = blockIdx.x * blockDim.x + threadIdx.x;
    if (i <= NN) g_deg[i] = 0;
    if (i < SCANB) g_scanstate[i] = 0ULL;
}

__global__ void count_deg(const int* __restrict__ dst) {
    int e = blockIdx.x * blockDim.x + threadIdx.x;
    if (e < EE) atomicAdd(&g_deg[dst[e]], 1);
}

__global__ void scan_lookback() {
    int b = blockIdx.x, tid = threadIdx.x;
    int lane = tid & 31, warp = tid >> 5;
    int i = b * 128 + tid;
    int v = (i < NN) ? g_deg[i] : 0;
    int incl = v;
#pragma unroll
    for (int o = 1; o < 32; o <<= 1) {
        int t = __shfl_up_sync(0xffffffffu, incl, o);
        if (lane >= o) incl += t;
    }
    __shared__ int wsum[4];
    __shared__ int s_prev;
    if (lane == 31) wsum[warp] = incl;
    __syncthreads();
    int wbase = 0;
    for (int w = 0; w < warp; w++) wbase += wsum[w];
    int incl_b = wbase + incl;
    int total = wsum[0] + wsum[1] + wsum[2] + wsum[3];

    if (tid == 0) {
        if (b == 0) {
            atomicExch(&g_scanstate[0], (2ULL << 32) | (unsigned)total);
            s_prev = 0;
        } else {
            atomicExch(&g_scanstate[b], (1ULL << 32) | (unsigned)total);
            long long run = 0;
            int j = b - 1;
            while (1) {
                unsigned long long st;
                do { st = atomicOr(&g_scanstate[j], 0ULL); } while ((st >> 32) == 0ULL);
                run += (long long)(st & 0xffffffffULL);
                if ((st >> 32) == 2ULL) break;
                j--;
            }
            s_prev = (int)run;
            atomicExch(&g_scanstate[b], (2ULL << 32) | (unsigned)(run + total));
        }
    }
    __syncthreads();
    int excl = s_prev + incl_b - v;
    if (i < NN) {
        g_off[i] = excl;
        g_cur[i] = excl;
        if (i == NN - 1) g_off[NN] = excl + v;
    }
}

__global__ void scatter_csr(const int* __restrict__ src, const int* __restrict__ dst,
                            const int* __restrict__ et) {
    int e = blockIdx.x * blockDim.x + threadIdx.x;
    if (e >= EE) return;
    int pos = atomicAdd(&g_cur[dst[e]], 1);
    g_esd[pos] = src[e] | (et[e] << 20);
}

// ---------------- GEMM helpers ----------------
__device__ __forceinline__ uint32_t h2u(__half2 h) {
    return *reinterpret_cast<uint32_t*>(&h);
}
__device__ __forceinline__ void ldsm_x4(uint32_t* r, uint32_t addr) {
    asm volatile("ldmatrix.sync.aligned.m8n8.x4.shared.b16 {%0,%1,%2,%3}, [%4];"
                 : "=r"(r[0]), "=r"(r[1]), "=r"(r[2]), "=r"(r[3]) : "r"(addr));
}
__device__ __forceinline__ void ldsm_x4_t(uint32_t* r, uint32_t addr) {
    asm volatile("ldmatrix.sync.aligned.m8n8.x4.trans.shared.b16 {%0,%1,%2,%3}, [%4];"
                 : "=r"(r[0]), "=r"(r[1]), "=r"(r[2]), "=r"(r[3]) : "r"(addr));
}
__device__ __forceinline__ void hmma(float* c, const uint32_t* a, uint32_t b0, uint32_t b1) {
    asm volatile(
        "mma.sync.aligned.m16n8k16.row.col.f32.f16.f16.f32 "
        "{%0,%1,%2,%3}, {%4,%5,%6,%7}, {%8,%9}, {%0,%1,%2,%3};\n"
        : "+f"(c[0]), "+f"(c[1]), "+f"(c[2]), "+f"(c[3])
        : "r"(a[0]), "r"(a[1]), "r"(a[2]), "r"(a[3]), "r"(b0), "r"(b1));
}
__device__ __forceinline__ void cp16(uint32_t dst, const void* src) {
    asm volatile("cp.async.cg.shared.global [%0], [%1], 16;" :: "r"(dst), "l"(src));
}
__device__ __forceinline__ void cp_commit() {
    asm volatile("cp.async.commit_group;" ::: "memory");
}
__device__ __forceinline__ void cp_wait2() {
    asm volatile("cp.async.wait_group 2;" ::: "memory");
}

// ---------------- narrow GEMM (BN=128, 4-stage) — all GEMMs ----------------
#define STAGES   4
#define A_STAGE  10240       // 128 rows * 80 B
#define B_STAGE  8704        // 32 rows * 272 B
#define SMEM_SZ  (STAGES * (A_STAGE + B_STAGE))   // 75776

__global__ __launch_bounds__(256)
void mma_gemm(const __half* __restrict__ A, const __half* __restrict__ B,
              const float* __restrict__ bias, __half* __restrict__ C,
              int K, int Nn, int doRelu) {
    extern __shared__ char smem[];
    const uint32_t smem_u = (uint32_t)__cvta_generic_to_shared(smem);
    const uint32_t as_u = smem_u;
    const uint32_t bs_u = smem_u + STAGES * A_STAGE;

    const int tid = threadIdx.x;
    const int warp = tid >> 5, lane = tid & 31;
    const int g = lane >> 2, tg = lane & 3;
    const int warpM = warp >> 1, warpN = warp & 1;
    const int rowBase = blockIdx.y * 128, colBase = blockIdx.x * 128;

    const int a_row = tid >> 1, a_ch = (tid & 1) * 2;
    const uint32_t a_dst = as_u + a_row * 80 + a_ch * 16;
    const __half* a_src = A + (size_t)(rowBase + a_row) * K + a_ch * 8;
    const int b_row = tid >> 3, b_ch = (tid & 7) * 2;
    const uint32_t b_dst = bs_u + b_row * 272 + b_ch * 16;
    const __half* b_src = B + (size_t)b_row * Nn + colBase + b_ch * 8;

    const int lm_row = ((lane >> 3) & 1) * 8 + (lane & 7);
    const int lm_hi  = (lane >= 16) ? 8 : 0;

    float acc[2][8][4];
#pragma unroll
    for (int mi = 0; mi < 2; mi++)
#pragma unroll
        for (int ni = 0; ni < 8; ni++)
#pragma unroll
            for (int r = 0; r < 4; r++) acc[mi][ni][r] = 0.0f;

    const int nk = K / 32;

#define ISSUE(S, T)                                                        \
    {                                                                      \
        int k0 = (T) * 32;                                                 \
        cp16(a_dst + (S) * A_STAGE, a_src + k0);                           \
        cp16(a_dst + (S) * A_STAGE + 16, a_src + k0 + 8);                  \
        cp16(b_dst + (S) * B_STAGE, b_src + (size_t)k0 * Nn);              \
        cp16(b_dst + (S) * B_STAGE + 16, b_src + (size_t)k0 * Nn + 8);     \
    }

#pragma unroll
    for (int s = 0; s < STAGES - 1; s++) {
        if (s < nk) ISSUE(s, s)
        cp_commit();
    }

    for (int t = 0; t < nk; t++) {
        cp_wait2();
        __syncthreads();
        if (t + STAGES - 1 < nk) ISSUE((t + STAGES - 1) & 3, t + STAGES - 1)
        cp_commit();

        const uint32_t as_s = as_u + (t & 3) * A_STAGE;
        const uint32_t bs_s = bs_u + (t & 3) * B_STAGE;
#pragma unroll
        for (int ks = 0; ks < 2; ks++) {
            uint32_t a[2][4];
#pragma unroll
            for (int mi = 0; mi < 2; mi++) {
                int row = warpM * 32 + mi * 16 + lm_row;
                ldsm_x4(a[mi], as_s + row * 80 + (ks * 16 + lm_hi) * 2);
            }
            uint32_t bf[4][4];
#pragma unroll
            for (int nj = 0; nj < 4; nj++) {
                int col = warpN * 64 + nj * 16 + lm_hi;
                ldsm_x4_t(bf[nj], bs_s + (ks * 16 + lm_row) * 272 + col * 2);
            }
#pragma unroll
            for (int ni = 0; ni < 8; ni++) {
                uint32_t b0 = bf[ni >> 1][(ni & 1) * 2];
                uint32_t b1 = bf[ni >> 1][(ni & 1) * 2 + 1];
#pragma unroll
                for (int mi = 0; mi < 2; mi++)
                    hmma(acc[mi][ni], a[mi], b0, b1);
            }
        }
    }
#undef ISSUE

#pragma unroll
    for (int mi = 0; mi < 2; mi++) {
        int r0 = rowBase + warpM * 32 + mi * 16 + g;
#pragma unroll
        for (int ni = 0; ni < 8; ni++) {
            int c0 = colBase + warpN * 64 + ni * 8 + tg * 2;
            float bb0 = bias ? bias[c0] : 0.0f;
            float bb1 = bias ? bias[c0 + 1] : 0.0f;
            float v0 = acc[mi][ni][0] + bb0;
            float v1 = acc[mi][ni][1] + bb1;
            float v2 = acc[mi][ni][2] + bb0;
            float v3 = acc[mi][ni][3] + bb1;
            if (doRelu) {
                v0 = fmaxf(v0, 0.f); v1 = fmaxf(v1, 0.f);
                v2 = fmaxf(v2, 0.f); v3 = fmaxf(v3, 0.f);
            }
            __half2 p0 = __floats2half2_rn(v0, v1);
            __half2 p1 = __floats2half2_rn(v2, v3);
            *(uint32_t*)(C + (size_t)r0 * Nn + c0) = h2u(p0);
            *(uint32_t*)(C + (size_t)(r0 + 8) * Nn + c0) = h2u(p1);
        }
    }
}

// ---------------- a_s/a_d for layer 0 from g_xh ----------------
__global__ void asd0() {
    int n = blockIdx.x * 8 + (threadIdx.x >> 5);
    int lane = threadIdx.x & 31;
    if (n >= NN) return;
    uint2 u = *(const uint2*)(g_xh + (size_t)n * DD + lane * 4);
    float2 xa = __half22float2(*(__half2*)&u.x);
    float2 xb = __half22float2(*(__half2*)&u.y);
    float r[8];
#pragma unroll
    for (int h = 0; h < 8; h++) {
        const float* w = &g_ws[0][h][lane * 4];
        float p = xa.x * w[0] + xa.y * w[1] + xb.x * w[2] + xb.y * w[3];
#pragma unroll
        for (int o = 16; o; o >>= 1) p += __shfl_xor_sync(0xffffffffu, p, o);
        r[h] = p;
    }
    if (lane < 8) g_asd[0][n * 8 + lane] = r[lane];
}

// fused GAT: staged edge metadata + cooperative weights + gather + softmax + epilogue
__global__ void gat_node(const float* __restrict__ bias, float* __restrict__ outF, int L) {
    int n = blockIdx.x;
    int tid = threadIdx.x;      // 128
    int head = tid >> 5;
    __shared__ float tab_sm[RR * HH];
    __shared__ float s_adn[4];
    __shared__ int   sval[128];
    __shared__ float wbuf[512];
    __shared__ float sbuf[512];
    const float* asd = g_asd[L];
    if (tid < RR * HH) tab_sm[tid] = ((const float*)g_tab)[L * RR * HH + tid];
    if (tid < 4) s_adn[tid] = asd[n * 8 + 4 + tid];
    __syncthreads();

    int p0 = g_off[n], p1 = g_off[n + 1];
    int deg = p1 - p0;
    const uint2* hrow = (const uint2*)g_hHh;
    float4 acc = make_float4(0.f, 0.f, 0.f, 0.f);
    float wsum = 0.0f, tsum = 0.0f;

    for (int base = p0; base < p1; base += 128) {
        int m = min(128, p1 - base);
        if (tid < m) {
            int v = g_esd[base + tid];
            sval[tid] = v;
            int s = v & 0xFFFFF, t = v >> 20;
            float4 as4 = *(const float4*)(asd + s * 8);
            const float* tb = &tab_sm[t * HH];
            float r0 = as4.x + s_adn[0] + tb[0]; r0 = r0 > 0.f ? r0 : 0.2f * r0;
            float r1 = as4.y + s_adn[1] + tb[1]; r1 = r1 > 0.f ? r1 : 0.2f * r1;
            float r2 = as4.z + s_adn[2] + tb[2]; r2 = r2 > 0.f ? r2 : 0.2f * r2;
            float r3 = as4.w + s_adn[3] + tb[3]; r3 = r3 > 0.f ? r3 : 0.2f * r3;
            float4 w4 = make_float4(__expf(r0), __expf(r1), __expf(r2), __expf(r3));
            *(float4*)&wbuf[tid * 4] = w4;
        }
        __syncthreads();
        int e = 0;
        for (; e + 4 <= m; e += 4) {
            int v0 = sval[e], v1 = sval[e + 1], v2 = sval[e + 2], v3 = sval[e + 3];
            float w0 = wbuf[e * 4 + head];
            float w1 = wbuf[(e + 1) * 4 + head];
            float w2 = wbuf[(e + 2) * 4 + head];
            float w3 = wbuf[(e + 3) * 4 + head];
            uint2 u0 = hrow[(size_t)(v0 & 0xFFFFF) * 128 + tid];
            uint2 u1 = hrow[(size_t)(v1 & 0xFFFFF) * 128 + tid];
            uint2 u2 = hrow[(size_t)(v2 & 0xFFFFF) * 128 + tid];
            uint2 u3 = hrow[(size_t)(v3 & 0xFFFFF) * 128 + tid];
            wsum += (w0 + w1) + (w2 + w3);
            tsum += tab_sm[(v0 >> 20) * HH + head] + tab_sm[(v1 >> 20) * HH + head]
                  + tab_sm[(v2 >> 20) * HH + head] + tab_sm[(v3 >> 20) * HH + head];
            float2 a0 = __half22float2(*(__half2*)&u0.x), b0 = __half22float2(*(__half2*)&u0.y);
            float2 a1 = __half22float2(*(__half2*)&u1.x), b1 = __half22float2(*(__half2*)&u1.y);
            float2 a2 = __half22float2(*(__half2*)&u2.x), b2 = __half22float2(*(__half2*)&u2.y);
            float2 a3 = __half22float2(*(__half2*)&u3.x), b3 = __half22float2(*(__half2*)&u3.y);
            acc.x += w0 * a0.x + w1 * a1.x + w2 * a2.x + w3 * a3.x;
            acc.y += w0 * a0.y + w1 * a1.y + w2 * a2.y + w3 * a3.y;
            acc.z += w0 * b0.x + w1 * b1.x + w2 * b2.x + w3 * b3.x;
            acc.w += w0 * b0.y + w1 * b1.y + w2 * b2.y + w3 * b3.y;
        }
        for (; e < m; e++) {
            int v = sval[e];
            int s = v & 0xFFFFF;
            float w = wbuf[e * 4 + head];
            uint2 u = hrow[(size_t)s * 128 + tid];
            wsum += w;
            tsum += tab_sm[(v >> 20) * HH + head];
            float2 f0 = __half22float2(*(__half2*)&u.x);
            float2 f1 = __half22float2(*(__half2*)&u.y);
            acc.x += w * f0.x; acc.y += w * f0.y;
            acc.z += w * f1.x; acc.w += w * f1.y;
        }
        __syncthreads();
    }
    // self loop
    {
        float asn = asd[n * 8 + head];
        float adn = s_adn[head];
        float sr = asn + adn + tsum / fmaxf((float)deg, 1.0f);
        sr = sr > 0.f ? sr : 0.2f * sr;
        float wself = __expf(sr);
        uint2 u = hrow[(size_t)n * 128 + tid];
        float2 f0 = __half22float2(*(__half2*)&u.x);
        float2 f1 = __half22float2(*(__half2*)&u.y);
        acc.x += wself * f0.x; acc.y += wself * f0.y;
        acc.z += wself * f1.x; acc.w += wself * f1.y;
        float inv = 1.0f / (wsum + wself + 1e-16f);
        acc.x *= inv; acc.y *= inv; acc.z *= inv; acc.w *= inv;
    }
    *(float4*)&sbuf[tid * 4] = acc;
    __syncthreads();
    if (tid < 32) {
        float ov[4];
#pragma unroll
        for (int j = 0; j < 4; j++) {
            int d = tid * 4 + j;
            float v = 0.25f * (sbuf[d] + sbuf[128 + d] + sbuf[256 + d] + sbuf[384 + d]) + bias[d];
            v = fmaxf(v, 0.0f);
            ov[j] = v;
        }
        if (L == 0) {
            __half2 p0 = __floats2half2_rn(ov[0], ov[1]);
            __half2 p1 = __floats2half2_rn(ov[2], ov[3]);
            uint2 pk = make_uint2(h2u(p0), h2u(p1));
            *(uint2*)(g_xh + (size_t)n * DD + tid * 4) = pk;
            float r[8];
#pragma unroll
            for (int h = 0; h < 8; h++) {
                const float* w = &g_ws[1][h][tid * 4];
                float pp = ov[0] * w[0] + ov[1] * w[1] + ov[2] * w[2] + ov[3] * w[3];
#pragma unroll
                for (int o = 16; o; o >>= 1) pp += __shfl_xor_sync(0xffffffffu, pp, o);
                r[h] = pp;
            }
            if (tid < 8) g_asd[1][n * 8 + tid] = r[tid];
        } else {
#pragma unroll
            for (int j = 0; j < 4; j++)
                outF[(size_t)n * DD + tid * 4 + j] = ov[j];
        }
    }
}

// ---------------- host ----------------
template <typename T>
static T* symaddr(const void* s) {
    void* p = nullptr;
    cudaGetSymbolAddress(&p, s);
    return (T*)p;
}

extern "C" void kernel_launch(void* const* d_in, const int* in_sizes, int n_in,
                              void* d_out, int out_size) {
    const float* x   = (const float*)d_in[0];
    const int*   ei  = (const int*)d_in[1];
    const int*   et  = (const int*)d_in[2];
    const float* w1  = (const float*)d_in[3];
    const float* b1  = (const float*)d_in[4];
    const float* w2  = (const float*)d_in[5];
    const float* b2  = (const float*)d_in[6];
    const float* rel = (const float*)d_in[7];
    const float* lin[2]  = {(const float*)d_in[8],  (const float*)d_in[14]};
    const float* line[2] = {(const float*)d_in[9],  (const float*)d_in[15]};
    const float* atts[2] = {(const float*)d_in[10], (const float*)d_in[16]};
    const float* attd[2] = {(const float*)d_in[11], (const float*)d_in[17]};
    const float* atte[2] = {(const float*)d_in[12], (const float*)d_in[18]};
    const float* bias[2] = {(const float*)d_in[13], (const float*)d_in[19]};
    const int* srcp = ei;
    const int* dstp = ei + EE;

    __half* pxp  = symaddr<__half>(g_xp);
    __half* ph1  = symaddr<__half>(g_h1h);
    __half* pxh  = symaddr<__half>(g_xh);
    __half* phH  = symaddr<__half>(g_hHh);
    __half* pw1  = symaddr<__half>(g_w1h);
    __half* pw2  = symaddr<__half>(g_w2h);
    __half* pl0  = symaddr<__half>(g_linh);
    __half* pl1  = pl0 + (size_t)DD * HH * DD;

    static cudaStream_t s2 = nullptr;
    static cudaEvent_t evFork = nullptr, evJoin = nullptr;
    if (!s2) {
        cudaStreamCreateWithFlags(&s2, cudaStreamNonBlocking);
        cudaEventCreateWithFlags(&evFork, cudaEventDisableTiming);
        cudaEventCreateWithFlags(&evJoin, cudaEventDisableTiming);
    }

    cudaFuncSetAttribute(mma_gemm, cudaFuncAttributeMaxDynamicSharedMemorySize, SMEM_SZ);

    // fork: CSR chain on s2, dense chain on default stream
    cudaEventRecord(evFork, 0);
    cudaStreamWaitEvent(s2, evFork, 0);

    zero_deg<<<(NN + 256) / 256, 256, 0, s2>>>();
    count_deg<<<(EE + 255) / 256, 256, 0, s2>>>(dstp);
    scan_lookback<<<SCANB, 128, 0, s2>>>();
    scatter_csr<<<(EE + 255) / 256, 256, 0, s2>>>(srcp, dstp, et);
    cudaEventRecord(evJoin, s2);

    setup<<<PADB + 1 + 8 + C1B + C2B + C3B, 256>>>(
        x, rel, line[0], atte[0], line[1], atte[1],
        lin[0], atts[0], attd[0], lin[1], atts[1], attd[1], w1, w2);
    mma_gemm<<<dim3(HID / 128, NPAD / 128), 256, SMEM_SZ>>>(pxp, pw1, b1, ph1, KP1, HID, 1);
    mma_gemm<<<dim3(DD / 128, NPAD / 128), 256, SMEM_SZ>>>(ph1, pw2, b2, pxh, HID, DD, 0);
    asd0<<<(NN + 7) / 8, 256>>>();
    mma_gemm<<<dim3((HH * DD) / 128, NPAD / 128), 256, SMEM_SZ>>>(pxh, pl0, nullptr, phH, DD, HH * DD, 0);

    // join before first CSR consumer
    cudaStreamWaitEvent(0, evJoin, 0);

    gat_node<<<NN, 128>>>(bias[0], (float*)d_out, 0);
    mma_gemm<<<dim3((HH * DD) / 128, NPAD / 128), 256, SMEM_SZ>>>(pxh, pl1, nullptr, phH, DD, HH * DD, 0);
    gat_node<<<NN, 128>>>(bias[1], (float*)d_out, 1);
}

// round 15
// speedup vs baseline: 1.1717x; 1.0304x over previous
#include <cuda_runtime.h>
#include <cuda_fp16.h>
#include <math.h>
#include <stdint.h>

#define NN    20000
#define NPAD  20096            // 157*128
#define EE    320000
#define FIN   518
#define KP1   544
#define DD    128
#define EDIM  32
#define HH    4
#define RR    26
#define HID   256
#define SCANB ((NN + 127) / 128)
#define PADB  ((int)(((size_t)NPAD * KP1) / 256))
#define C1B   ((KP1 * HID) / 256)
#define C2B   ((HID * DD) / 256)
#define C3B   ((2 * DD * HH * DD) / 256)

// ---------------- scratch ----------------
__device__ __half g_xp[(size_t)NPAD * KP1];
__device__ __half g_h1h[(size_t)NPAD * HID];
__device__ __half g_xh[(size_t)NPAD * DD];
__device__ __align__(16) __half g_hHh[(size_t)NPAD * HH * DD];
__device__ __half g_w1h[(size_t)KP1 * HID];
__device__ __half g_w2h[(size_t)HID * DD];
__device__ __half g_linh[2][(size_t)DD * HH * DD];
__device__ __align__(16) float g_asd[2][NN * 8];
__device__ __align__(16) float g_tab[2][RR][HH];
__device__ float g_ws[2][8][DD];
__device__ int   g_deg[NN + 1];
__device__ int   g_off[NN + 1];
__device__ int   g_cur[NN];
__device__ int   g_esd[EE];          // packed: src | (et << 20)
__device__ unsigned long long g_scanstate[SCANB];

// ---------------- setup (dense chain) ----------------
__global__ void setup(const float* __restrict__ x, const float* __restrict__ rel,
                      const float* __restrict__ line0, const float* __restrict__ atte0,
                      const float* __restrict__ line1, const float* __restrict__ atte1,
                      const float* __restrict__ lin0, const float* __restrict__ atts0,
                      const float* __restrict__ attd0,
                      const float* __restrict__ lin1, const float* __restrict__ atts1,
                      const float* __restrict__ attd1,
                      const float* __restrict__ w1, const float* __restrict__ w2) {
    int b = blockIdx.x, tid = threadIdx.x;
    if (b < PADB) {
        size_t i = (size_t)b * 256 + tid;
        int n = (int)(i / KP1), c = (int)(i % KP1);
        float v = (n < NN && c < FIN) ? x[(size_t)n * FIN + c] : 0.0f;
        g_xp[i] = __float2half(v);
        return;
    }
    b -= PADB;
    if (b == 0) {
        __shared__ float we[2][HH][EDIM];
        if (tid < 2 * HH * EDIM) {
            int L = tid >> 7, rem = tid & 127;
            int h = rem / EDIM, c = rem % EDIM;
            const float* line = L ? line1 : line0;
            const float* atte = L ? atte1 : atte0;
            float s = 0.0f;
            for (int d = 0; d < DD; d++)
                s += line[(size_t)c * (HH * DD) + h * DD + d] * atte[h * DD + d];
            we[L][h][c] = s;
        }
        __syncthreads();
        if (tid < 2 * RR * HH) {
            int L = tid / (RR * HH), rem = tid % (RR * HH);
            int r = rem / HH, h = rem % HH;
            float s = 0.0f;
            for (int c = 0; c < EDIM; c++)
                s += rel[r * EDIM + c] * we[L][h][c];
            g_tab[L][r][h] = s;
        }
        return;
    }
    b -= 1;
    if (b < 8) {
        int idx = b * 256 + tid;
        if (idx < 2 * 8 * DD) {
            int L = idx / (8 * DD), rem = idx % (8 * DD);
            int h8 = rem / DD, k = rem % DD;
            const float* lin = L ? lin1 : lin0;
            const float* att;
            int h = h8 & 3;
            if (h8 < 4) att = L ? atts1 : atts0;
            else        att = L ? attd1 : attd0;
            float s = 0.0f;
            for (int d = 0; d < DD; d++)
                s += lin[(size_t)k * (HH * DD) + h * DD + d] * att[h * DD + d];
            g_ws[L][h8][k] = s;
        }
        return;
    }
    b -= 8;
    if (b < C1B) {
        int i = b * 256 + tid;
        int k = i / HID, n = i % HID;
        g_w1h[i] = __float2half(k < FIN ? w1[(size_t)k * HID + n] : 0.0f);
        return;
    }
    b -= C1B;
    if (b < C2B) {
        int i = b * 256 + tid;
        g_w2h[i] = __float2half(w2[i]);
        return;
    }
    b -= C2B;
    {
        int i = b * 256 + tid;
        int L = i / (DD * HH * DD), r = i % (DD * HH * DD);
        const float* lin = L ? lin1 : lin0;
        g_linh[L][r] = __float2half(lin[r]);
    }
}

// ---------------- CSR chain (stream 2) ----------------
__global__ void zero_deg() {
    int i = blockIdx.x * blockDim.x + threadIdx.x;
    if (i <= NN) g_deg[i] = 0;
    if (i < SCANB) g_scanstate[i] = 0ULL;
}

__global__ void count_deg(const int* __restrict__ dst) {
    int e = blockIdx.x * blockDim.x + threadIdx.x;
    if (e < EE) atomicAdd(&g_deg[dst[e]], 1);
}

__global__ void scan_lookback() {
    int b = blockIdx.x, tid = threadIdx.x;
    int lane = tid & 31, warp = tid >> 5;
    int i = b * 128 + tid;
    int v = (i < NN) ? g_deg[i] : 0;
    int incl = v;
#pragma unroll
    for (int o = 1; o < 32; o <<= 1) {
        int t = __shfl_up_sync(0xffffffffu, incl, o);
        if (lane >= o) incl += t;
    }
    __shared__ int wsum[4];
    __shared__ int s_prev;
    if (lane == 31) wsum[warp] = incl;
    __syncthreads();
    int wbase = 0;
    for (int w = 0; w < warp; w++) wbase += wsum[w];
    int incl_b = wbase + incl;
    int total = wsum[0] + wsum[1] + wsum[2] + wsum[3];

    if (tid == 0) {
        if (b == 0) {
            atomicExch(&g_scanstate[0], (2ULL << 32) | (unsigned)total);
            s_prev = 0;
        } else {
            atomicExch(&g_scanstate[b], (1ULL << 32) | (unsigned)total);
            long long run = 0;
            int j = b - 1;
            while (1) {
                unsigned long long st;
                do { st = atomicOr(&g_scanstate[j], 0ULL); } while ((st >> 32) == 0ULL);
                run += (long long)(st & 0xffffffffULL);
                if ((st >> 32) == 2ULL) break;
                j--;
            }
            s_prev = (int)run;
            atomicExch(&g_scanstate[b], (2ULL << 32) | (unsigned)(run + total));
        }
    }
    __syncthreads();
    int excl = s_prev + incl_b - v;
    if (i < NN) {
        g_off[i] = excl;
        g_cur[i] = excl;
        if (i == NN - 1) g_off[NN] = excl + v;
    }
}

__global__ void scatter_csr(const int* __restrict__ src, const int* __restrict__ dst,
                            const int* __restrict__ et) {
    int e = blockIdx.x * blockDim.x + threadIdx.x;
    if (e >= EE) return;
    int pos = atomicAdd(&g_cur[dst[e]], 1);
    g_esd[pos] = src[e] | (et[e] << 20);
}

// ---------------- GEMM helpers ----------------
__device__ __forceinline__ uint32_t h2u(__half2 h) {
    return *reinterpret_cast<uint32_t*>(&h);
}
__device__ __forceinline__ void ldsm_x4(uint32_t* r, uint32_t addr) {
    asm volatile("ldmatrix.sync.aligned.m8n8.x4.shared.b16 {%0,%1,%2,%3}, [%4];"
                 : "=r"(r[0]), "=r"(r[1]), "=r"(r[2]), "=r"(r[3]) : "r"(addr));
}
__device__ __forceinline__ void ldsm_x4_t(uint32_t* r, uint32_t addr) {
    asm volatile("ldmatrix.sync.aligned.m8n8.x4.trans.shared.b16 {%0,%1,%2,%3}, [%4];"
                 : "=r"(r[0]), "=r"(r[1]), "=r"(r[2]), "=r"(r[3]) : "r"(addr));
}
__device__ __forceinline__ void hmma(float* c, const uint32_t* a, uint32_t b0, uint32_t b1) {
    asm volatile(
        "mma.sync.aligned.m16n8k16.row.col.f32.f16.f16.f32 "
        "{%0,%1,%2,%3}, {%4,%5,%6,%7}, {%8,%9}, {%0,%1,%2,%3};\n"
        : "+f"(c[0]), "+f"(c[1]), "+f"(c[2]), "+f"(c[3])
        : "r"(a[0]), "r"(a[1]), "r"(a[2]), "r"(a[3]), "r"(b0), "r"(b1));
}
__device__ __forceinline__ void cp16(uint32_t dst, const void* src) {
    asm volatile("cp.async.cg.shared.global [%0], [%1], 16;" :: "r"(dst), "l"(src));
}
__device__ __forceinline__ void cp_commit() {
    asm volatile("cp.async.commit_group;" ::: "memory");
}
__device__ __forceinline__ void cp_wait2() {
    asm volatile("cp.async.wait_group 2;" ::: "memory");
}

// ---------------- narrow GEMM (BN=128, 4-stage) — all GEMMs ----------------
#define STAGES   4
#define A_STAGE  10240       // 128 rows * 80 B
#define B_STAGE  8704        // 32 rows * 272 B
#define SMEM_SZ  (STAGES * (A_STAGE + B_STAGE))   // 75776

__global__ __launch_bounds__(256)
void mma_gemm(const __half* __restrict__ A, const __half* __restrict__ B,
              const float* __restrict__ bias, __half* __restrict__ C,
              int K, int Nn, int doRelu) {
    extern __shared__ char smem[];
    const uint32_t smem_u = (uint32_t)__cvta_generic_to_shared(smem);
    const uint32_t as_u = smem_u;
    const uint32_t bs_u = smem_u + STAGES * A_STAGE;

    const int tid = threadIdx.x;
    const int warp = tid >> 5, lane = tid & 31;
    const int g = lane >> 2, tg = lane & 3;
    const int warpM = warp >> 1, warpN = warp & 1;
    const int rowBase = blockIdx.y * 128, colBase = blockIdx.x * 128;

    const int a_row = tid >> 1, a_ch = (tid & 1) * 2;
    const uint32_t a_dst = as_u + a_row * 80 + a_ch * 16;
    const __half* a_src = A + (size_t)(rowBase + a_row) * K + a_ch * 8;
    const int b_row = tid >> 3, b_ch = (tid & 7) * 2;
    const uint32_t b_dst = bs_u + b_row * 272 + b_ch * 16;
    const __half* b_src = B + (size_t)b_row * Nn + colBase + b_ch * 8;

    const int lm_row = ((lane >> 3) & 1) * 8 + (lane & 7);
    const int lm_hi  = (lane >= 16) ? 8 : 0;

    float acc[2][8][4];
#pragma unroll
    for (int mi = 0; mi < 2; mi++)
#pragma unroll
        for (int ni = 0; ni < 8; ni++)
#pragma unroll
            for (int r = 0; r < 4; r++) acc[mi][ni][r] = 0.0f;

    const int nk = K / 32;

#define ISSUE(S, T)                                                        \
    {                                                                      \
        int k0 = (T) * 32;                                                 \
        cp16(a_dst + (S) * A_STAGE, a_src + k0);                           \
        cp16(a_dst + (S) * A_STAGE + 16, a_src + k0 + 8);                  \
        cp16(b_dst + (S) * B_STAGE, b_src + (size_t)k0 * Nn);              \
        cp16(b_dst + (S) * B_STAGE + 16, b_src + (size_t)k0 * Nn + 8);     \
    }

#pragma unroll
    for (int s = 0; s < STAGES - 1; s++) {
        if (s < nk) ISSUE(s, s)
        cp_commit();
    }

    for (int t = 0; t < nk; t++) {
        cp_wait2();
        __syncthreads();
        if (t + STAGES - 1 < nk) ISSUE((t + STAGES - 1) & 3, t + STAGES - 1)
        cp_commit();

        const uint32_t as_s = as_u + (t & 3) * A_STAGE;
        const uint32_t bs_s = bs_u + (t & 3) * B_STAGE;
#pragma unroll
        for (int ks = 0; ks < 2; ks++) {
            uint32_t a[2][4];
#pragma unroll
            for (int mi = 0; mi < 2; mi++) {
                int row = warpM * 32 + mi * 16 + lm_row;
                ldsm_x4(a[mi], as_s + row * 80 + (ks * 16 + lm_hi) * 2);
            }
            uint32_t bf[4][4];
#pragma unroll
            for (int nj = 0; nj < 4; nj++) {
                int col = warpN * 64 + nj * 16 + lm_hi;
                ldsm_x4_t(bf[nj], bs_s + (ks * 16 + lm_row) * 272 + col * 2);
            }
#pragma unroll
            for (int ni = 0; ni < 8; ni++) {
                uint32_t b0 = bf[ni >> 1][(ni & 1) * 2];
                uint32_t b1 = bf[ni >> 1][(ni & 1) * 2 + 1];
#pragma unroll
                for (int mi = 0; mi < 2; mi++)
                    hmma(acc[mi][ni], a[mi], b0, b1);
            }
        }
    }
#undef ISSUE

#pragma unroll
    for (int mi = 0; mi < 2; mi++) {
        int r0 = rowBase + warpM * 32 + mi * 16 + g;
#pragma unroll
        for (int ni = 0; ni < 8; ni++) {
            int c0 = colBase + warpN * 64 + ni * 8 + tg * 2;
            float bb0 = bias ? bias[c0] : 0.0f;
            float bb1 = bias ? bias[c0 + 1] : 0.0f;
            float v0 = acc[mi][ni][0] + bb0;
            float v1 = acc[mi][ni][1] + bb1;
            float v2 = acc[mi][ni][2] + bb0;
            float v3 = acc[mi][ni][3] + bb1;
            if (doRelu) {
                v0 = fmaxf(v0, 0.f); v1 = fmaxf(v1, 0.f);
                v2 = fmaxf(v2, 0.f); v3 = fmaxf(v3, 0.f);
            }
            __half2 p0 = __floats2half2_rn(v0, v1);
            __half2 p1 = __floats2half2_rn(v2, v3);
            *(uint32_t*)(C + (size_t)r0 * Nn + c0) = h2u(p0);
            *(uint32_t*)(C + (size_t)(r0 + 8) * Nn + c0) = h2u(p1);
        }
    }
}

// ---------------- a_s/a_d for layer 0 from g_xh ----------------
__global__ void asd0() {
    int n = blockIdx.x * 8 + (threadIdx.x >> 5);
    int lane = threadIdx.x & 31;
    if (n >= NN) return;
    uint2 u = *(const uint2*)(g_xh + (size_t)n * DD + lane * 4);
    float2 xa = __half22float2(*(__half2*)&u.x);
    float2 xb = __half22float2(*(__half2*)&u.y);
    float r[8];
#pragma unroll
    for (int h = 0; h < 8; h++) {
        const float* w = &g_ws[0][h][lane * 4];
        float p = xa.x * w[0] + xa.y * w[1] + xb.x * w[2] + xb.y * w[3];
#pragma unroll
        for (int o = 16; o; o >>= 1) p += __shfl_xor_sync(0xffffffffu, p, o);
        r[h] = p;
    }
    if (lane < 8) g_asd[0][n * 8 + lane] = r[lane];
}

// fused GAT: 2 edges across 128 threads, uint4 gathers, unrolled x4 pairs
__global__ void gat_node(const float* __restrict__ bias, float* __restrict__ outF, int L) {
    int n = blockIdx.x;
    int tid = threadIdx.x;        // 128
    int u = tid & 63;             // 16B chunk index within row (64 x uint4 = 1KB)
    int par = tid >> 6;           // edge parity (0/1)
    int head = u >> 4;            // 16 uint4 per head
    __shared__ float tab_sm[RR * HH];
    __shared__ float s_adn[4];
    __shared__ int   sval[128];
    __shared__ float wbuf[512];
    __shared__ float s_ws[2][4], s_ts[2][4];
    __shared__ float sbuf[1024];
    const float* asd = g_asd[L];
    if (tid < RR * HH) tab_sm[tid] = ((const float*)g_tab)[L * RR * HH + tid];
    if (tid < 4) s_adn[tid] = asd[n * 8 + 4 + tid];
    __syncthreads();

    int p0 = g_off[n], p1 = g_off[n + 1];
    int deg = p1 - p0;
    const uint4* hrow = (const uint4*)g_hHh;      // row stride = 64 uint4
    float acc[8];
#pragma unroll
    for (int j = 0; j < 8; j++) acc[j] = 0.0f;
    float wsum = 0.0f, tsum = 0.0f;

#define ACC_EDGE(Q, W)                                                     \
    {                                                                      \
        float2 f0 = __half22float2(*(__half2*)&(Q).x);                     \
        float2 f1 = __half22float2(*(__half2*)&(Q).y);                     \
        float2 f2 = __half22float2(*(__half2*)&(Q).z);                     \
        float2 f3 = __half22float2(*(__half2*)&(Q).w);                     \
        acc[0] += (W) * f0.x; acc[1] += (W) * f0.y;                        \
        acc[2] += (W) * f1.x; acc[3] += (W) * f1.y;                        \
        acc[4] += (W) * f2.x; acc[5] += (W) * f2.y;                        \
        acc[6] += (W) * f3.x; acc[7] += (W) * f3.y;                        \
    }

    for (int base = p0; base < p1; base += 128) {
        int m = min(128, p1 - base);
        if (tid < m) {
            int v = g_esd[base + tid];
            sval[tid] = v;
            int s = v & 0xFFFFF, t = v >> 20;
            float4 as4 = *(const float4*)(asd + s * 8);
            const float* tb = &tab_sm[t * HH];
            float r0 = as4.x + s_adn[0] + tb[0]; r0 = r0 > 0.f ? r0 : 0.2f * r0;
            float r1 = as4.y + s_adn[1] + tb[1]; r1 = r1 > 0.f ? r1 : 0.2f * r1;
            float r2 = as4.z + s_adn[2] + tb[2]; r2 = r2 > 0.f ? r2 : 0.2f * r2;
            float r3 = as4.w + s_adn[3] + tb[3]; r3 = r3 > 0.f ? r3 : 0.2f * r3;
            float4 w4 = make_float4(__expf(r0), __expf(r1), __expf(r2), __expf(r3));
            *(float4*)&wbuf[tid * 4] = w4;
        }
        __syncthreads();
        int p = 0;
        for (; p + 8 <= m; p += 8) {
            int e0 = p + par, e1 = p + 2 + par, e2 = p + 4 + par, e3 = p + 6 + par;
            int v0 = sval[e0], v1 = sval[e1], v2 = sval[e2], v3 = sval[e3];
            uint4 q0 = hrow[(size_t)(v0 & 0xFFFFF) * 64 + u];
            uint4 q1 = hrow[(size_t)(v1 & 0xFFFFF) * 64 + u];
            uint4 q2 = hrow[(size_t)(v2 & 0xFFFFF) * 64 + u];
            uint4 q3 = hrow[(size_t)(v3 & 0xFFFFF) * 64 + u];
            float w0 = wbuf[e0 * 4 + head], w1 = wbuf[e1 * 4 + head];
            float w2 = wbuf[e2 * 4 + head], w3 = wbuf[e3 * 4 + head];
            wsum += (w0 + w1) + (w2 + w3);
            tsum += tab_sm[(v0 >> 20) * HH + head] + tab_sm[(v1 >> 20) * HH + head]
                  + tab_sm[(v2 >> 20) * HH + head] + tab_sm[(v3 >> 20) * HH + head];
            ACC_EDGE(q0, w0) ACC_EDGE(q1, w1) ACC_EDGE(q2, w2) ACC_EDGE(q3, w3)
        }
        for (; p < m; p += 2) {
            int e = p + par;
            if (e < m) {
                int v = sval[e];
                uint4 q = hrow[(size_t)(v & 0xFFFFF) * 64 + u];
                float w = wbuf[e * 4 + head];
                wsum += w;
                tsum += tab_sm[(v >> 20) * HH + head];
                ACC_EDGE(q, w)
            }
        }
        __syncthreads();
    }

    // combine parity-group sums per head
    if ((u & 15) == 0) { s_ws[par][head] = wsum; s_ts[par][head] = tsum; }
    __syncthreads();
    float wsum_t = s_ws[0][head] + s_ws[1][head];
    float tsum_t = s_ts[0][head] + s_ts[1][head];

    // self loop
    {
        float asn = asd[n * 8 + head];
        float adn = s_adn[head];
        float sr = asn + adn + tsum_t / fmaxf((float)deg, 1.0f);
        sr = sr > 0.f ? sr : 0.2f * sr;
        float wself = __expf(sr);
        if (par == 0) {
            uint4 q = hrow[(size_t)n * 64 + u];
            ACC_EDGE(q, wself)
        }
        float inv = 1.0f / (wsum_t + wself + 1e-16f);
#pragma unroll
        for (int j = 0; j < 8; j++) acc[j] *= inv;
    }
#undef ACC_EDGE

    *(float4*)&sbuf[tid * 8]     = *(float4*)&acc[0];
    *(float4*)&sbuf[tid * 8 + 4] = *(float4*)&acc[4];
    __syncthreads();
    if (tid < 32) {
        float ov[4];
#pragma unroll
        for (int j = 0; j < 4; j++) {
            int d = tid * 4 + j;
            int ui = d >> 3, jj = d & 7;
            float s = 0.0f;
#pragma unroll
            for (int h = 0; h < 4; h++) {
                int uu = h * 16 + ui;
                s += sbuf[uu * 8 + jj] + sbuf[(64 + uu) * 8 + jj];
            }
            float v = 0.25f * s + bias[d];
            v = fmaxf(v, 0.0f);
            ov[j] = v;
        }
        if (L == 0) {
            __half2 p0 = __floats2half2_rn(ov[0], ov[1]);
            __half2 p1 = __floats2half2_rn(ov[2], ov[3]);
            uint2 pk = make_uint2(h2u(p0), h2u(p1));
            *(uint2*)(g_xh + (size_t)n * DD + tid * 4) = pk;
            float r[8];
#pragma unroll
            for (int h = 0; h < 8; h++) {
                const float* w = &g_ws[1][h][tid * 4];
                float pp = ov[0] * w[0] + ov[1] * w[1] + ov[2] * w[2] + ov[3] * w[3];
#pragma unroll
                for (int o = 16; o; o >>= 1) pp += __shfl_xor_sync(0xffffffffu, pp, o);
                r[h] = pp;
            }
            if (tid < 8) g_asd[1][n * 8 + tid] = r[tid];
        } else {
#pragma unroll
            for (int j = 0; j < 4; j++)
                outF[(size_t)n * DD + tid * 4 + j] = ov[j];
        }
    }
}

// ---------------- host ----------------
template <typename T>
static T* symaddr(const void* s) {
    void* p = nullptr;
    cudaGetSymbolAddress(&p, s);
    return (T*)p;
}

extern "C" void kernel_launch(void* const* d_in, const int* in_sizes, int n_in,
                              void* d_out, int out_size) {
    const float* x   = (const float*)d_in[0];
    const int*   ei  = (const int*)d_in[1];
    const int*   et  = (const int*)d_in[2];
    const float* w1  = (const float*)d_in[3];
    const float* b1  = (const float*)d_in[4];
    const float* w2  = (const float*)d_in[5];
    const float* b2  = (const float*)d_in[6];
    const float* rel = (const float*)d_in[7];
    const float* lin[2]  = {(const float*)d_in[8],  (const float*)d_in[14]};
    const float* line[2] = {(const float*)d_in[9],  (const float*)d_in[15]};
    const float* atts[2] = {(const float*)d_in[10], (const float*)d_in[16]};
    const float* attd[2] = {(const float*)d_in[11], (const float*)d_in[17]};
    const float* atte[2] = {(const float*)d_in[12], (const float*)d_in[18]};
    const float* bias[2] = {(const float*)d_in[13], (const float*)d_in[19]};
    const int* srcp = ei;
    const int* dstp = ei + EE;

    __half* pxp  = symaddr<__half>(g_xp);
    __half* ph1  = symaddr<__half>(g_h1h);
    __half* pxh  = symaddr<__half>(g_xh);
    __half* phH  = symaddr<__half>(g_hHh);
    __half* pw1  = symaddr<__half>(g_w1h);
    __half* pw2  = symaddr<__half>(g_w2h);
    __half* pl0  = symaddr<__half>(g_linh);
    __half* pl1  = pl0 + (size_t)DD * HH * DD;

    static cudaStream_t s2 = nullptr;
    static cudaEvent_t evFork = nullptr, evJoin = nullptr, evG2 = nullptr;
    if (!s2) {
        cudaStreamCreateWithFlags(&s2, cudaStreamNonBlocking);
        cudaEventCreateWithFlags(&evFork, cudaEventDisableTiming);
        cudaEventCreateWithFlags(&evJoin, cudaEventDisableTiming);
        cudaEventCreateWithFlags(&evG2, cudaEventDisableTiming);
    }

    cudaFuncSetAttribute(mma_gemm, cudaFuncAttributeMaxDynamicSharedMemorySize, SMEM_SZ);

    // fork: CSR chain + asd0 on s2, dense chain on default stream
    cudaEventRecord(evFork, 0);
    cudaStreamWaitEvent(s2, evFork, 0);

    zero_deg<<<(NN + 256) / 256, 256, 0, s2>>>();
    count_deg<<<(EE + 255) / 256, 256, 0, s2>>>(dstp);
    scan_lookback<<<SCANB, 128, 0, s2>>>();
    scatter_csr<<<(EE + 255) / 256, 256, 0, s2>>>(srcp, dstp, et);

    setup<<<PADB + 1 + 8 + C1B + C2B + C3B, 256>>>(
        x, rel, line[0], atte[0], line[1], atte[1],
        lin[0], atts[0], attd[0], lin[1], atts[1], attd[1], w1, w2);
    mma_gemm<<<dim3(HID / 128, NPAD / 128), 256, SMEM_SZ>>>(pxp, pw1, b1, ph1, KP1, HID, 1);
    mma_gemm<<<dim3(DD / 128, NPAD / 128), 256, SMEM_SZ>>>(ph1, pw2, b2, pxh, HID, DD, 0);
    cudaEventRecord(evG2, 0);

    // asd0 on s2 after GEMM2 (overlaps with GEMM3-L0 on stream 0)
    cudaStreamWaitEvent(s2, evG2, 0);
    asd0<<<(NN + 7) / 8, 256, 0, s2>>>();
    cudaEventRecord(evJoin, s2);

    mma_gemm<<<dim3((HH * DD) / 128, NPAD / 128), 256, SMEM_SZ>>>(pxh, pl0, nullptr, phH, DD, HH * DD, 0);

    // join before first CSR/asd consumer
    cudaStreamWaitEvent(0, evJoin, 0);

    gat_node<<<NN, 128>>>(bias[0], (float*)d_out, 0);
    mma_gemm<<<dim3((HH * DD) / 128, NPAD / 128), 256, SMEM_SZ>>>(pxh, pl1, nullptr, phH, DD, HH * DD, 0);
    gat_node<<<NN, 128>>>(bias[1], (float*)d_out, 1);
}